// round 16
// baseline (speedup 1.0000x reference)
#include <cuda_runtime.h>
#include <cuda_fp16.h>
#include <cstdint>

#define B_  4
#define T_  2048
#define E_  1024
#define H_  16
#define HS_ 64
#define M_  (B_*T_)    // 8192
#define FF_ (4*E_)     // 4096

typedef unsigned long long u64;
typedef __half fp16;

// weight pre-scale (keeps small weights out of fp16 subnormal range)
#define WSC   64.0f
#define WSI   0.015625f               // 1/64
#define QSI   (0.015625f * 0.03125f)  // 1/64 * E^-0.5

// ======================= scratch pool (__device__ global) =======================
#define SZ_HB   ((size_t)M_*E_*2)
#define SZ_F32  ((size_t)M_*E_*4)
#define SZ_FFB  ((size_t)M_*FF_*2)
#define SZ_WB   ((size_t)E_*E_*2)
#define SZ_W1B  ((size_t)E_*FF_*2)

constexpr size_t O_H    = 0;
constexpr size_t O_Q    = O_H    + SZ_HB;
constexpr size_t O_K    = O_Q    + SZ_HB;
constexpr size_t O_V    = O_K    + SZ_HB;
constexpr size_t O_Y    = O_V    + SZ_HB;
constexpr size_t O_X2   = O_Y    + SZ_HB;
constexpr size_t O_FF   = O_X2   + SZ_F32;
constexpr size_t O_WQ   = O_FF   + SZ_FFB;
constexpr size_t O_WK   = O_WQ   + SZ_WB;
constexpr size_t O_WV   = O_WK   + SZ_WB;
constexpr size_t O_WO   = O_WV   + SZ_WB;
constexpr size_t O_W1   = O_WO   + SZ_WB;
constexpr size_t O_W2   = O_W1   + SZ_W1B;
constexpr size_t POOLSZ = O_W2   + SZ_W1B;

__device__ __align__(1024) unsigned char g_pool[POOLSZ];

// ======================= PTX helpers =======================
__device__ __forceinline__ uint32_t s2u(const void* p){
    uint32_t a;
    asm("{ .reg .u64 t; cvta.to.shared.u64 t, %1; cvt.u32.u64 %0, t; }" : "=r"(a) : "l"(p));
    return a;
}
__device__ __forceinline__ void cp16(uint32_t s, const void* g){
    asm volatile("cp.async.cg.shared.global [%0], [%1], 16;" :: "r"(s), "l"(g));
}
__device__ __forceinline__ void ldm4(uint32_t (&r)[4], uint32_t a){
    asm volatile("ldmatrix.sync.aligned.m8n8.x4.shared.b16 {%0,%1,%2,%3}, [%4];"
                 : "=r"(r[0]), "=r"(r[1]), "=r"(r[2]), "=r"(r[3]) : "r"(a));
}
__device__ __forceinline__ void ldm4t(uint32_t (&r)[4], uint32_t a){
    asm volatile("ldmatrix.sync.aligned.m8n8.x4.trans.shared.b16 {%0,%1,%2,%3}, [%4];"
                 : "=r"(r[0]), "=r"(r[1]), "=r"(r[2]), "=r"(r[3]) : "r"(a));
}
__device__ __forceinline__ void mma_f16(float (&c)[4], const uint32_t* a, uint32_t b0, uint32_t b1){
    asm volatile(
        "mma.sync.aligned.m16n8k16.row.col.f32.f16.f16.f32 "
        "{%0,%1,%2,%3}, {%4,%5,%6,%7}, {%8,%9}, {%0,%1,%2,%3};"
        : "+f"(c[0]), "+f"(c[1]), "+f"(c[2]), "+f"(c[3])
        : "r"(a[0]), "r"(a[1]), "r"(a[2]), "r"(a[3]), "r"(b0), "r"(b1));
}
__device__ __forceinline__ uint32_t packh(float lo_val, float hi_val){
    uint32_t r;
    asm("cvt.rn.f16x2.f32 %0, %1, %2;" : "=r"(r) : "f"(hi_val), "f"(lo_val));
    return r;
}

// ======================= LayerNorm -> single fp16 =======================
__global__ __launch_bounds__(256) void ln_kernel(
    const float* __restrict__ X, const float* __restrict__ w,
    fp16* __restrict__ O)
{
    int row = blockIdx.x;
    int tid = threadIdx.x;
    const float* x = X + (size_t)row * E_;

    float4 v = *(const float4*)(x + tid * 4);
    float s  = v.x + v.y + v.z + v.w;
    float sq = v.x*v.x + v.y*v.y + v.z*v.z + v.w*v.w;

    #pragma unroll
    for (int o = 16; o; o >>= 1) {
        s  += __shfl_xor_sync(0xFFFFFFFFu, s,  o);
        sq += __shfl_xor_sync(0xFFFFFFFFu, sq, o);
    }
    __shared__ float ss[8], ssq[8], red[2];
    int wid = tid >> 5, lane = tid & 31;
    if (lane == 0) { ss[wid] = s; ssq[wid] = sq; }
    __syncthreads();
    if (tid == 0) {
        float a = 0.f, b = 0.f;
        #pragma unroll
        for (int i = 0; i < 8; i++) { a += ss[i]; b += ssq[i]; }
        float mean = a * (1.0f / E_);
        float var  = b * (1.0f / E_) - mean * mean;
        red[0] = mean;
        red[1] = rsqrtf(var + 1e-5f);
    }
    __syncthreads();
    float mean = red[0], rs = red[1];
    float4 wv = *(const float4*)(w + tid * 4);
    float o0 = (v.x - mean) * rs * wv.x;
    float o1 = (v.y - mean) * rs * wv.y;
    float o2 = (v.z - mean) * rs * wv.z;
    float o3 = (v.w - mean) * rs * wv.w;

    __half2 p0 = __floats2half2_rn(o0, o1);
    __half2 p1 = __floats2half2_rn(o2, o3);
    size_t off = (size_t)row * E_ + tid * 4;
    *(__half2*)(O + off)     = p0;
    *(__half2*)(O + off + 2) = p1;
}

// ======================= weight transpose + convert (x64 scale) ================
__global__ __launch_bounds__(256) void wconv_kernel(
    const float* __restrict__ W, fp16* __restrict__ Wo,
    int K, int N)
{
    __shared__ float t[32][33];
    int n0 = blockIdx.x * 32, k0 = blockIdx.y * 32;
    int tx = threadIdx.x, ty0 = threadIdx.y;
    #pragma unroll
    for (int dy = 0; dy < 32; dy += 8) {
        int ty = ty0 + dy;
        t[ty][tx] = W[(size_t)(k0 + ty) * N + n0 + tx];
    }
    __syncthreads();
    #pragma unroll
    for (int dy = 0; dy < 32; dy += 8) {
        int ty = ty0 + dy;
        Wo[(size_t)(n0 + ty) * K + k0 + tx] = __float2half_rn(t[tx][ty] * WSC);
    }
}

// ======================= HMMA GEMM (fp16 1-pass, 3-stage pipeline) ============
// BK=64, 110.6KB smem (3 stages), 2 CTAs/SM.
// OP: 1 = acc*WSI+bias+res -> f32; 2 = relu(acc*WSI+bias) -> fp16;
// OP: 3 = fused QKV: sel0 -> q (x QSI); sel1/2 -> k/v (x WSI)
#define BM 128
#define BN 128
#define BK 64
#define ROWB   144
#define MTILE  (128*ROWB)     // 18432
#define BUFSZ  (2*MTILE)      // 36864  (A, B)
#define NSTAGE 3
#define SMEM_SZ (NSTAGE*BUFSZ) // 110592

template<int OP>
__global__ __launch_bounds__(256, 2) void gemm_tc(
    const fp16* __restrict__ A,
    const fp16* __restrict__ B0, const fp16* __restrict__ B1, const fp16* __restrict__ B2,
    const float* __restrict__ bias, const float* __restrict__ res,
    float* __restrict__ C,
    fp16* __restrict__ C0, fp16* __restrict__ C1, fp16* __restrict__ C2,
    int M, int N, int K)
{
    extern __shared__ __align__(128) unsigned char smem[];
    uint32_t sb = s2u(smem);
    int tid = threadIdx.x;
    int lane = tid & 31, wid = tid >> 5;
    int warp_m = wid & 1, warp_n = wid >> 1;

    int sel = 0, bxi = blockIdx.x;
    if (OP == 3) { sel = blockIdx.x >> 3; bxi = blockIdx.x & 7; }
    int bx = bxi * BN, by = blockIdx.y * BM;

    const fp16* Bp = (OP == 3) ? (sel == 0 ? B0 : sel == 1 ? B1 : B2) : B0;
    fp16* Cout = (OP == 3) ? (sel == 0 ? C0 : sel == 1 ? C1 : C2) : C0;
    float oscale = (OP == 3 && sel == 0) ? QSI : WSI;

    int chb = tid * 4;
    int lrow[4], lc16[4];
    uint32_t soff[4];
    #pragma unroll
    for (int i = 0; i < 4; i++) {
        lrow[i] = (chb + i) >> 3;
        lc16[i] = (chb + i) & 7;
        soff[i] = (uint32_t)(lrow[i] * ROWB + lc16[i] * 16);
    }

    const fp16* gA = A  + (size_t)(by) * K;
    const fp16* gB = Bp + (size_t)(bx) * K;

    float acc[4][4][4];
    #pragma unroll
    for (int i = 0; i < 4; i++)
        #pragma unroll
        for (int j = 0; j < 4; j++)
            #pragma unroll
            for (int q = 0; q < 4; q++) acc[i][j][q] = 0.f;

    int nt = K / BK;

    auto issue_tile = [&](int t, int buf) {
        uint32_t base = sb + buf * BUFSZ;
        int k0 = t * BK;
        #pragma unroll
        for (int i = 0; i < 4; i++) {
            size_t go = (size_t)lrow[i] * K + k0 + lc16[i] * 8;
            cp16(base + soff[i],         gA + go);
            cp16(base + MTILE + soff[i], gB + go);
        }
        asm volatile("cp.async.commit_group;" ::: "memory");
    };

    issue_tile(0, 0);
    issue_tile(1, 1);

    uint32_t a_row = (uint32_t)(warp_m * 64 + (lane & 15));
    uint32_t a_cb  = (uint32_t)((lane >> 4) * 16);
    uint32_t b_row = (uint32_t)(warp_n * 32 + (lane & 7) + ((lane >> 4) & 1) * 8);
    uint32_t b_cb  = (uint32_t)(((lane >> 3) & 1) * 16);

    for (int t = 0; t < nt; t++) {
        if (t + 2 < nt) {
            issue_tile(t + 2, (t + 2) % NSTAGE);
            asm volatile("cp.async.wait_group 2;" ::: "memory");
        } else if (t + 1 < nt) {
            asm volatile("cp.async.wait_group 1;" ::: "memory");
        } else {
            asm volatile("cp.async.wait_group 0;" ::: "memory");
        }
        __syncthreads();

        uint32_t base = sb + (t % NSTAGE) * BUFSZ;
        uint32_t sA = base;
        uint32_t sB = base + MTILE;

        #pragma unroll
        for (int s = 0; s < 4; s++) {
            uint32_t kb = (uint32_t)(s * 32);

            uint32_t af[4][4];
            #pragma unroll
            for (int mt = 0; mt < 4; mt++)
                ldm4(af[mt], sA + (a_row + mt * 16) * ROWB + kb + a_cb);
            uint32_t bf[2][4];
            #pragma unroll
            for (int ntp = 0; ntp < 2; ntp++)
                ldm4(bf[ntp], sB + (b_row + ntp * 16) * ROWB + kb + b_cb);
            #pragma unroll
            for (int mt = 0; mt < 4; mt++)
                #pragma unroll
                for (int ntp = 0; ntp < 2; ntp++)
                    #pragma unroll
                    for (int hf = 0; hf < 2; hf++)
                        mma_f16(acc[mt][ntp*2+hf], af[mt], bf[ntp][hf*2], bf[ntp][hf*2+1]);
        }
        __syncthreads();
    }

    // -------- epilogue --------
    int er = by + warp_m * 64 + (lane >> 2);
    int ec = bx + warp_n * 32 + (lane & 3) * 2;
    #pragma unroll
    for (int mt = 0; mt < 4; mt++) {
        #pragma unroll
        for (int half = 0; half < 2; half++) {
            int row = er + mt * 16 + half * 8;
            #pragma unroll
            for (int ntj = 0; ntj < 4; ntj++) {
                int col = ec + ntj * 8;
                float v0 = acc[mt][ntj][half*2];
                float v1 = acc[mt][ntj][half*2+1];
                if (OP == 1) {
                    float2 rv = *(const float2*)&res[(size_t)row * N + col];
                    float2 bv = *(const float2*)&bias[col];
                    *(float2*)&C[(size_t)row * N + col] =
                        make_float2(v0 * WSI + bv.x + rv.x, v1 * WSI + bv.y + rv.y);
                } else if (OP == 2) {
                    float2 bv = *(const float2*)&bias[col];
                    float w0 = fmaxf(v0 * WSI + bv.x, 0.0f);
                    float w1 = fmaxf(v1 * WSI + bv.y, 0.0f);
                    *(__half2*)&C0[(size_t)row * N + col] = __floats2half2_rn(w0, w1);
                } else {
                    *(__half2*)&Cout[(size_t)row * N + col] =
                        __floats2half2_rn(v0 * oscale, v1 * oscale);
                }
            }
        }
    }
}

// ======================= Tensor-core causal flash attention ====================
// q, K, V single fp16: QK^T 1-pass, PV 1-pass. 3-stage KV pipeline, 73.7KB smem.
// LPT scheduling: heaviest q-tiles (largest qt) launched first.
#define AROWB 144
#define AQTILE (128*AROWB)    // 18432
#define AKTILE (64*AROWB)     // 9216
#define ASM_Q  0
#define ASM_KV AQTILE
#define AKV_K  0
#define AKV_V  AKTILE
#define AKVSTAGE (2*AKTILE)   // 18432
#define ANSTAGE 3
#define ASMEM (AQTILE + ANSTAGE*AKVSTAGE)  // 73728

__global__ __launch_bounds__(256, 2) void attn_tc(
    const fp16* __restrict__ Q,
    const fp16* __restrict__ Kg,
    const fp16* __restrict__ V,
    fp16* __restrict__ Y)
{
    extern __shared__ __align__(128) unsigned char asmem[];
    uint32_t sb = s2u(asmem);
    int tid = threadIdx.x, lane = tid & 31, wid = tid >> 5;
    int qt = gridDim.x - 1 - blockIdx.x;   // LPT: big tiles first
    int bh = blockIdx.y;
    int b = bh >> 4, h = bh & 15;

    size_t rowbase = (size_t)b * T_;
    size_t qoff = (rowbase + qt * 128) * E_ + h * HS_;

    {
        int chb = tid * 4;
        #pragma unroll
        for (int i = 0; i < 4; i++) {
            int lr = (chb + i) >> 3;
            int lc = (chb + i) & 7;
            uint32_t so = (uint32_t)(lr * AROWB + lc * 16);
            cp16(sb + ASM_Q + so, Q + qoff + (size_t)lr * E_ + lc * 8);
        }
    }
    asm volatile("cp.async.commit_group;" ::: "memory");

    int kv_row = tid >> 2;
    int kv_c   = (tid & 3) * 2;
    uint32_t kv_so = (uint32_t)(kv_row * AROWB + kv_c * 16);

    auto load_kv = [&](int kt, int buf) {
        size_t ko = (rowbase + kt * 64 + kv_row) * E_ + h * HS_ + kv_c * 8;
        uint32_t base = sb + ASM_KV + buf * AKVSTAGE + kv_so;
        cp16(base + AKV_K,      Kg + ko);
        cp16(base + AKV_K + 16, Kg + ko + 8);
        cp16(base + AKV_V,      V + ko);
        cp16(base + AKV_V + 16, V + ko + 8);
        asm volatile("cp.async.commit_group;" ::: "memory");
    };
    int nkt = 2 * qt + 2;
    load_kv(0, 0);
    if (nkt > 1) load_kv(1, 1);

    // wait for Q (allow the KV stages to stay in flight)
    if (nkt > 1) { asm volatile("cp.async.wait_group 2;" ::: "memory"); }
    else         { asm volatile("cp.async.wait_group 1;" ::: "memory"); }
    __syncthreads();

    uint32_t a_row = (uint32_t)(wid * 16 + (lane & 15));
    uint32_t a_cb  = (uint32_t)((lane >> 4) * 16);
    uint32_t qf[4][4];
    #pragma unroll
    for (int s = 0; s < 4; s++)
        ldm4(qf[s], sb + ASM_Q + a_row * AROWB + s * 32 + a_cb);

    float oacc[8][4];
    #pragma unroll
    for (int i = 0; i < 8; i++)
        #pragma unroll
        for (int j = 0; j < 4; j++) oacc[i][j] = 0.f;
    float m0 = -1e30f, m1 = -1e30f, l0 = 0.f, l1 = 0.f;

    uint32_t b_rowo = (uint32_t)((lane & 7) + ((lane >> 4) & 1) * 8);
    uint32_t b_cbo  = (uint32_t)(((lane >> 3) & 1) * 16);
    uint32_t v_rowo = (uint32_t)(lane & 15);
    uint32_t v_cbo  = (uint32_t)(((lane >> 4) & 1) * 16);

    for (int kt = 0; kt < nkt; kt++) {
        if (kt + 2 < nkt) {
            load_kv(kt + 2, (kt + 2) % ANSTAGE);
            asm volatile("cp.async.wait_group 2;" ::: "memory");
        } else if (kt + 1 < nkt) {
            asm volatile("cp.async.wait_group 1;" ::: "memory");
        } else {
            asm volatile("cp.async.wait_group 0;" ::: "memory");
        }
        __syncthreads();
        uint32_t kb = sb + ASM_KV + (kt % ANSTAGE) * AKVSTAGE;

        float sacc[8][4];
        #pragma unroll
        for (int j = 0; j < 8; j++)
            #pragma unroll
            for (int q = 0; q < 4; q++) sacc[j][q] = 0.f;

        #pragma unroll
        for (int s = 0; s < 4; s++) {
            #pragma unroll
            for (int np = 0; np < 4; np++) {
                uint32_t bo = (uint32_t)(np * 16 + b_rowo) * AROWB + s * 32 + b_cbo;
                uint32_t kf[4];
                ldm4(kf, kb + AKV_K + bo);
                #pragma unroll
                for (int hf = 0; hf < 2; hf++)
                    mma_f16(sacc[np*2+hf], qf[s], kf[hf*2], kf[hf*2+1]);
            }
        }

        if (kt >= 2 * qt) {
            int qr0 = qt * 128 + wid * 16 + (lane >> 2);
            int kc  = kt * 64 + (lane & 3) * 2;
            #pragma unroll
            for (int j = 0; j < 8; j++) {
                int k0i = kc + j * 8;
                if (k0i     > qr0)     sacc[j][0] = -1e30f;
                if (k0i + 1 > qr0)     sacc[j][1] = -1e30f;
                if (k0i     > qr0 + 8) sacc[j][2] = -1e30f;
                if (k0i + 1 > qr0 + 8) sacc[j][3] = -1e30f;
            }
        }

        float mx0 = m0, mx1 = m1;
        #pragma unroll
        for (int j = 0; j < 8; j++) {
            mx0 = fmaxf(mx0, fmaxf(sacc[j][0], sacc[j][1]));
            mx1 = fmaxf(mx1, fmaxf(sacc[j][2], sacc[j][3]));
        }
        mx0 = fmaxf(mx0, __shfl_xor_sync(0xFFFFFFFFu, mx0, 1));
        mx0 = fmaxf(mx0, __shfl_xor_sync(0xFFFFFFFFu, mx0, 2));
        mx1 = fmaxf(mx1, __shfl_xor_sync(0xFFFFFFFFu, mx1, 1));
        mx1 = fmaxf(mx1, __shfl_xor_sync(0xFFFFFFFFu, mx1, 2));
        float cor0 = __expf(m0 - mx0);
        float cor1 = __expf(m1 - mx1);
        m0 = mx0; m1 = mx1;
        float rs0 = 0.f, rs1 = 0.f;
        #pragma unroll
        for (int j = 0; j < 8; j++) {
            float p0 = __expf(sacc[j][0] - m0);
            float p1 = __expf(sacc[j][1] - m0);
            float p2 = __expf(sacc[j][2] - m1);
            float p3 = __expf(sacc[j][3] - m1);
            sacc[j][0] = p0; sacc[j][1] = p1; sacc[j][2] = p2; sacc[j][3] = p3;
            rs0 += p0 + p1; rs1 += p2 + p3;
        }
        rs0 += __shfl_xor_sync(0xFFFFFFFFu, rs0, 1);
        rs0 += __shfl_xor_sync(0xFFFFFFFFu, rs0, 2);
        rs1 += __shfl_xor_sync(0xFFFFFFFFu, rs1, 1);
        rs1 += __shfl_xor_sync(0xFFFFFFFFu, rs1, 2);
        l0 = l0 * cor0 + rs0;
        l1 = l1 * cor1 + rs1;
        #pragma unroll
        for (int dt = 0; dt < 8; dt++) {
            oacc[dt][0] *= cor0; oacc[dt][1] *= cor0;
            oacc[dt][2] *= cor1; oacc[dt][3] *= cor1;
        }

        #pragma unroll
        for (int s = 0; s < 4; s++) {
            uint32_t pah[4];
            #pragma unroll
            for (int tt = 0; tt < 2; tt++) {
                const float* sc = sacc[2*s + tt];
                pah[tt*2+0] = packh(sc[0], sc[1]);
                pah[tt*2+1] = packh(sc[2], sc[3]);
            }
            #pragma unroll
            for (int dc = 0; dc < 4; dc++) {
                uint32_t vo = (uint32_t)(s * 16 + v_rowo) * AROWB + dc * 32 + v_cbo;
                uint32_t vf[4];
                ldm4t(vf, kb + AKV_V + vo);
                mma_f16(oacc[dc*2+0], pah, vf[0], vf[1]);
                mma_f16(oacc[dc*2+1], pah, vf[2], vf[3]);
            }
        }
        __syncthreads();
    }

    float inv0 = 1.0f / l0;
    float inv1 = 1.0f / l1;
    int qr = qt * 128 + wid * 16 + (lane >> 2);
    size_t y0 = (rowbase + qr) * E_ + h * HS_ + (lane & 3) * 2;
    size_t y1 = y0 + (size_t)8 * E_;
    #pragma unroll
    for (int dt = 0; dt < 8; dt++) {
        *(__half2*)(Y + y0 + dt*8) = __floats2half2_rn(oacc[dt][0]*inv0, oacc[dt][1]*inv0);
        *(__half2*)(Y + y1 + dt*8) = __floats2half2_rn(oacc[dt][2]*inv1, oacc[dt][3]*inv1);
    }
}

// ======================= launch =======================
extern "C" void kernel_launch(void* const* d_in, const int* in_sizes, int n_in,
                              void* d_out, int out_size)
{
    const float* x    = (const float*)d_in[0];
    const float* Wq   = (const float*)d_in[1];
    const float* Wk   = (const float*)d_in[2];
    const float* Wv   = (const float*)d_in[3];
    const float* Wo   = (const float*)d_in[4];
    const float* bo   = (const float*)d_in[5];
    const float* ln1w = (const float*)d_in[6];
    const float* ln2w = (const float*)d_in[7];
    const float* W1   = (const float*)d_in[8];
    const float* b1   = (const float*)d_in[9];
    const float* W2   = (const float*)d_in[10];
    const float* b2   = (const float*)d_in[11];
    float* out = (float*)d_out;

    unsigned char* pool;
    cudaGetSymbolAddress((void**)&pool, g_pool);

    fp16*  hh   = (fp16*)(pool + O_H);
    fp16*  q    = (fp16*)(pool + O_Q);
    fp16*  k    = (fp16*)(pool + O_K);
    fp16*  v    = (fp16*)(pool + O_V);
    fp16*  y    = (fp16*)(pool + O_Y);
    float* x2   = (float*)(pool + O_X2);
    fp16*  ff   = (fp16*)(pool + O_FF);
    fp16*  wq   = (fp16*)(pool + O_WQ);
    fp16*  wk   = (fp16*)(pool + O_WK);
    fp16*  wv   = (fp16*)(pool + O_WV);
    fp16*  wo   = (fp16*)(pool + O_WO);
    fp16*  w1   = (fp16*)(pool + O_W1);
    fp16*  w2   = (fp16*)(pool + O_W2);

    cudaFuncSetAttribute((const void*)gemm_tc<1>, cudaFuncAttributeMaxDynamicSharedMemorySize, SMEM_SZ);
    cudaFuncSetAttribute((const void*)gemm_tc<2>, cudaFuncAttributeMaxDynamicSharedMemorySize, SMEM_SZ);
    cudaFuncSetAttribute((const void*)gemm_tc<3>, cudaFuncAttributeMaxDynamicSharedMemorySize, SMEM_SZ);
    cudaFuncSetAttribute((const void*)attn_tc,    cudaFuncAttributeMaxDynamicSharedMemorySize, ASMEM);

    dim3 tb(32, 8);
    dim3 gE (E_  / BN, M_ / BM);       // (8, 64)
    dim3 gQKV(3 * (E_ / BN), M_ / BM); // (24, 64)
    dim3 g4E(FF_ / BN, M_ / BM);       // (32, 64)

    // weight transpose + convert (x64 pre-scale)
    wconv_kernel<<<dim3(E_/32,  E_/32),  tb>>>(Wq, wq, E_,  E_);
    wconv_kernel<<<dim3(E_/32,  E_/32),  tb>>>(Wk, wk, E_,  E_);
    wconv_kernel<<<dim3(E_/32,  E_/32),  tb>>>(Wv, wv, E_,  E_);
    wconv_kernel<<<dim3(E_/32,  E_/32),  tb>>>(Wo, wo, E_,  E_);
    // h = LN1(x)
    ln_kernel<<<M_, 256>>>(x, ln1w, hh);
    // fused q,k,v projections -> single fp16 each (q pre-scaled by E^-0.5)
    gemm_tc<3><<<gQKV, 256, SMEM_SZ>>>(hh,
        wq, wk, wv,
        nullptr, nullptr, nullptr,
        q, k, v, M_, E_, E_);
    // y = causal attention
    attn_tc<<<dim3(T_/128, B_*H_), 256, ASMEM>>>(q, k, v, y);
    // MLP weight converts
    wconv_kernel<<<dim3(FF_/32, E_/32),  tb>>>(W1, w1, E_,  FF_);
    wconv_kernel<<<dim3(E_/32,  FF_/32), tb>>>(W2, w2, FF_, E_);
    // x2 = x + y @ Wo + bo
    gemm_tc<1><<<gE, 256, SMEM_SZ>>>(y,
        wo, wo, wo,
        bo, x, x2,
        nullptr, nullptr, nullptr, M_, E_, E_);
    // h2 = LN2(x2)
    ln_kernel<<<M_, 256>>>(x2, ln2w, hh);
    // ff = relu(h2 @ W1 + b1)
    gemm_tc<2><<<g4E, 256, SMEM_SZ>>>(hh,
        w1, w1, w1,
        b1, nullptr, nullptr,
        ff, nullptr, nullptr, M_, FF_, E_);
    // out = x2 + ff @ W2 + b2
    gemm_tc<1><<<gE, 256, SMEM_SZ>>>(ff,
        w2, w2, w2,
        b2, x2, out,
        nullptr, nullptr, nullptr, M_, E_, FF_);
}

// round 17
// speedup vs baseline: 1.0301x; 1.0301x over previous
#include <cuda_runtime.h>
#include <cuda_fp16.h>
#include <cstdint>

#define B_  4
#define T_  2048
#define E_  1024
#define H_  16
#define HS_ 64
#define M_  (B_*T_)    // 8192
#define FF_ (4*E_)     // 4096

typedef unsigned long long u64;
typedef __half fp16;

// weight pre-scale (keeps small weights out of fp16 subnormal range)
#define WSC   64.0f
#define WSI   0.015625f               // 1/64
#define QSI   (0.015625f * 0.03125f)  // 1/64 * E^-0.5

// ======================= scratch pool (__device__ global) =======================
#define SZ_HB   ((size_t)M_*E_*2)
#define SZ_F32  ((size_t)M_*E_*4)
#define SZ_FFB  ((size_t)M_*FF_*2)
#define SZ_WB   ((size_t)E_*E_*2)
#define SZ_W1B  ((size_t)E_*FF_*2)

constexpr size_t O_H    = 0;
constexpr size_t O_Q    = O_H    + SZ_HB;
constexpr size_t O_K    = O_Q    + SZ_HB;
constexpr size_t O_V    = O_K    + SZ_HB;
constexpr size_t O_Y    = O_V    + SZ_HB;
constexpr size_t O_X2   = O_Y    + SZ_HB;
constexpr size_t O_FF   = O_X2   + SZ_F32;
constexpr size_t O_WQ   = O_FF   + SZ_FFB;
constexpr size_t O_WK   = O_WQ   + SZ_WB;
constexpr size_t O_WV   = O_WK   + SZ_WB;
constexpr size_t O_WO   = O_WV   + SZ_WB;
constexpr size_t O_W1   = O_WO   + SZ_WB;
constexpr size_t O_W2   = O_W1   + SZ_W1B;
constexpr size_t POOLSZ = O_W2   + SZ_W1B;

__device__ __align__(1024) unsigned char g_pool[POOLSZ];

// ======================= PTX helpers =======================
__device__ __forceinline__ uint32_t s2u(const void* p){
    uint32_t a;
    asm("{ .reg .u64 t; cvta.to.shared.u64 t, %1; cvt.u32.u64 %0, t; }" : "=r"(a) : "l"(p));
    return a;
}
__device__ __forceinline__ void cp16(uint32_t s, const void* g){
    asm volatile("cp.async.cg.shared.global [%0], [%1], 16;" :: "r"(s), "l"(g));
}
__device__ __forceinline__ void ldm4(uint32_t (&r)[4], uint32_t a){
    asm volatile("ldmatrix.sync.aligned.m8n8.x4.shared.b16 {%0,%1,%2,%3}, [%4];"
                 : "=r"(r[0]), "=r"(r[1]), "=r"(r[2]), "=r"(r[3]) : "r"(a));
}
__device__ __forceinline__ void ldm4t(uint32_t (&r)[4], uint32_t a){
    asm volatile("ldmatrix.sync.aligned.m8n8.x4.trans.shared.b16 {%0,%1,%2,%3}, [%4];"
                 : "=r"(r[0]), "=r"(r[1]), "=r"(r[2]), "=r"(r[3]) : "r"(a));
}
__device__ __forceinline__ void mma_f16(float (&c)[4], const uint32_t* a, uint32_t b0, uint32_t b1){
    asm volatile(
        "mma.sync.aligned.m16n8k16.row.col.f32.f16.f16.f32 "
        "{%0,%1,%2,%3}, {%4,%5,%6,%7}, {%8,%9}, {%0,%1,%2,%3};"
        : "+f"(c[0]), "+f"(c[1]), "+f"(c[2]), "+f"(c[3])
        : "r"(a[0]), "r"(a[1]), "r"(a[2]), "r"(a[3]), "r"(b0), "r"(b1));
}
__device__ __forceinline__ uint32_t packh(float lo_val, float hi_val){
    uint32_t r;
    asm("cvt.rn.f16x2.f32 %0, %1, %2;" : "=r"(r) : "f"(hi_val), "f"(lo_val));
    return r;
}

// ======================= LayerNorm -> single fp16 =======================
__global__ __launch_bounds__(256) void ln_kernel(
    const float* __restrict__ X, const float* __restrict__ w,
    fp16* __restrict__ O)
{
    int row = blockIdx.x;
    int tid = threadIdx.x;
    const float* x = X + (size_t)row * E_;

    float4 v = *(const float4*)(x + tid * 4);
    float s  = v.x + v.y + v.z + v.w;
    float sq = v.x*v.x + v.y*v.y + v.z*v.z + v.w*v.w;

    #pragma unroll
    for (int o = 16; o; o >>= 1) {
        s  += __shfl_xor_sync(0xFFFFFFFFu, s,  o);
        sq += __shfl_xor_sync(0xFFFFFFFFu, sq, o);
    }
    __shared__ float ss[8], ssq[8], red[2];
    int wid = tid >> 5, lane = tid & 31;
    if (lane == 0) { ss[wid] = s; ssq[wid] = sq; }
    __syncthreads();
    if (tid == 0) {
        float a = 0.f, b = 0.f;
        #pragma unroll
        for (int i = 0; i < 8; i++) { a += ss[i]; b += ssq[i]; }
        float mean = a * (1.0f / E_);
        float var  = b * (1.0f / E_) - mean * mean;
        red[0] = mean;
        red[1] = rsqrtf(var + 1e-5f);
    }
    __syncthreads();
    float mean = red[0], rs = red[1];
    float4 wv = *(const float4*)(w + tid * 4);
    float o0 = (v.x - mean) * rs * wv.x;
    float o1 = (v.y - mean) * rs * wv.y;
    float o2 = (v.z - mean) * rs * wv.z;
    float o3 = (v.w - mean) * rs * wv.w;

    __half2 p0 = __floats2half2_rn(o0, o1);
    __half2 p1 = __floats2half2_rn(o2, o3);
    size_t off = (size_t)row * E_ + tid * 4;
    *(__half2*)(O + off)     = p0;
    *(__half2*)(O + off + 2) = p1;
}

// ============== fused weight transpose + convert (x64 scale), ALL weights ======
// flat tiles: [0,4096)   : Wq/Wk/Wv/Wo  (E x E, 1024 tiles each)
//             [4096,8192): W1 (K=E, N=FF, 4096 tiles)
//             [8192,12288): W2 (K=FF, N=E, 4096 tiles)
__global__ __launch_bounds__(256) void wconv_all(
    const float* __restrict__ Wq, const float* __restrict__ Wk,
    const float* __restrict__ Wv, const float* __restrict__ Wo,
    const float* __restrict__ W1, const float* __restrict__ W2,
    fp16* __restrict__ owq, fp16* __restrict__ owk,
    fp16* __restrict__ owv, fp16* __restrict__ owo,
    fp16* __restrict__ ow1, fp16* __restrict__ ow2)
{
    int idx = blockIdx.x;
    const float* W; fp16* O; int K, N, n0, k0;
    if (idx < 4096) {
        int w = idx >> 10, tix = idx & 1023;
        W = (w == 0) ? Wq : (w == 1) ? Wk : (w == 2) ? Wv : Wo;
        O = (w == 0) ? owq : (w == 1) ? owk : (w == 2) ? owv : owo;
        K = E_; N = E_;
        n0 = (tix & 31) * 32; k0 = (tix >> 5) * 32;
    } else if (idx < 8192) {
        int tix = idx - 4096;
        W = W1; O = ow1; K = E_; N = FF_;
        n0 = (tix & 127) * 32; k0 = (tix >> 7) * 32;
    } else {
        int tix = idx - 8192;
        W = W2; O = ow2; K = FF_; N = E_;
        n0 = (tix & 31) * 32; k0 = (tix >> 5) * 32;
    }

    __shared__ float t[32][33];
    int tx = threadIdx.x & 31, ty0 = threadIdx.x >> 5;
    #pragma unroll
    for (int dy = 0; dy < 32; dy += 8) {
        int ty = ty0 + dy;
        t[ty][tx] = W[(size_t)(k0 + ty) * N + n0 + tx];
    }
    __syncthreads();
    #pragma unroll
    for (int dy = 0; dy < 32; dy += 8) {
        int ty = ty0 + dy;
        O[(size_t)(n0 + ty) * K + k0 + tx] = __float2half_rn(t[tx][ty] * WSC);
    }
}

// ======================= HMMA GEMM (fp16 1-pass, 3-stage, 1 sync/tile) ========
// OP: 1 = acc*WSI+bias+res -> f32; 2 = relu(acc*WSI+bias) -> fp16;
// OP: 3 = fused QKV: sel0 -> q (x QSI); sel1/2 -> k/v (x WSI)
#define BM 128
#define BN 128
#define BK 64
#define ROWB   144
#define MTILE  (128*ROWB)     // 18432
#define BUFSZ  (2*MTILE)      // 36864  (A, B)
#define NSTAGE 3
#define SMEM_SZ (NSTAGE*BUFSZ) // 110592

template<int OP>
__global__ __launch_bounds__(256, 2) void gemm_tc(
    const fp16* __restrict__ A,
    const fp16* __restrict__ B0, const fp16* __restrict__ B1, const fp16* __restrict__ B2,
    const float* __restrict__ bias, const float* __restrict__ res,
    float* __restrict__ C,
    fp16* __restrict__ C0, fp16* __restrict__ C1, fp16* __restrict__ C2,
    int M, int N, int K)
{
    extern __shared__ __align__(128) unsigned char smem[];
    uint32_t sb = s2u(smem);
    int tid = threadIdx.x;
    int lane = tid & 31, wid = tid >> 5;
    int warp_m = wid & 1, warp_n = wid >> 1;

    int sel = 0, bxi = blockIdx.x;
    if (OP == 3) { sel = blockIdx.x >> 3; bxi = blockIdx.x & 7; }
    int bx = bxi * BN, by = blockIdx.y * BM;

    const fp16* Bp = (OP == 3) ? (sel == 0 ? B0 : sel == 1 ? B1 : B2) : B0;
    fp16* Cout = (OP == 3) ? (sel == 0 ? C0 : sel == 1 ? C1 : C2) : C0;
    float oscale = (OP == 3 && sel == 0) ? QSI : WSI;

    int chb = tid * 4;
    int lrow[4], lc16[4];
    uint32_t soff[4];
    #pragma unroll
    for (int i = 0; i < 4; i++) {
        lrow[i] = (chb + i) >> 3;
        lc16[i] = (chb + i) & 7;
        soff[i] = (uint32_t)(lrow[i] * ROWB + lc16[i] * 16);
    }

    const fp16* gA = A  + (size_t)(by) * K;
    const fp16* gB = Bp + (size_t)(bx) * K;

    float acc[4][4][4];
    #pragma unroll
    for (int i = 0; i < 4; i++)
        #pragma unroll
        for (int j = 0; j < 4; j++)
            #pragma unroll
            for (int q = 0; q < 4; q++) acc[i][j][q] = 0.f;

    int nt = K / BK;

    auto issue_tile = [&](int t, int buf) {
        uint32_t base = sb + buf * BUFSZ;
        int k0 = t * BK;
        #pragma unroll
        for (int i = 0; i < 4; i++) {
            size_t go = (size_t)lrow[i] * K + k0 + lc16[i] * 8;
            cp16(base + soff[i],         gA + go);
            cp16(base + MTILE + soff[i], gB + go);
        }
        asm volatile("cp.async.commit_group;" ::: "memory");
    };

    issue_tile(0, 0);
    issue_tile(1, 1);

    uint32_t a_row = (uint32_t)(warp_m * 64 + (lane & 15));
    uint32_t a_cb  = (uint32_t)((lane >> 4) * 16);
    uint32_t b_row = (uint32_t)(warp_n * 32 + (lane & 7) + ((lane >> 4) & 1) * 8);
    uint32_t b_cb  = (uint32_t)(((lane >> 3) & 1) * 16);

    for (int t = 0; t < nt; t++) {
        // wait until tile t landed
        if (t + 1 < nt) { asm volatile("cp.async.wait_group 1;" ::: "memory"); }
        else            { asm volatile("cp.async.wait_group 0;" ::: "memory"); }
        __syncthreads();
        // all warps done with tile t-1 -> safe to overwrite buffer (t+2)%3 == (t-1)%3
        if (t + 2 < nt) issue_tile(t + 2, (t + 2) % NSTAGE);

        uint32_t base = sb + (t % NSTAGE) * BUFSZ;
        uint32_t sA = base;
        uint32_t sB = base + MTILE;

        #pragma unroll
        for (int s = 0; s < 4; s++) {
            uint32_t kb = (uint32_t)(s * 32);

            uint32_t af[4][4];
            #pragma unroll
            for (int mt = 0; mt < 4; mt++)
                ldm4(af[mt], sA + (a_row + mt * 16) * ROWB + kb + a_cb);
            uint32_t bf[2][4];
            #pragma unroll
            for (int ntp = 0; ntp < 2; ntp++)
                ldm4(bf[ntp], sB + (b_row + ntp * 16) * ROWB + kb + b_cb);
            #pragma unroll
            for (int mt = 0; mt < 4; mt++)
                #pragma unroll
                for (int ntp = 0; ntp < 2; ntp++)
                    #pragma unroll
                    for (int hf = 0; hf < 2; hf++)
                        mma_f16(acc[mt][ntp*2+hf], af[mt], bf[ntp][hf*2], bf[ntp][hf*2+1]);
        }
    }

    // -------- epilogue (global writes only; no smem reuse -> no sync needed) ----
    int er = by + warp_m * 64 + (lane >> 2);
    int ec = bx + warp_n * 32 + (lane & 3) * 2;
    #pragma unroll
    for (int mt = 0; mt < 4; mt++) {
        #pragma unroll
        for (int half = 0; half < 2; half++) {
            int row = er + mt * 16 + half * 8;
            #pragma unroll
            for (int ntj = 0; ntj < 4; ntj++) {
                int col = ec + ntj * 8;
                float v0 = acc[mt][ntj][half*2];
                float v1 = acc[mt][ntj][half*2+1];
                if (OP == 1) {
                    float2 rv = *(const float2*)&res[(size_t)row * N + col];
                    float2 bv = *(const float2*)&bias[col];
                    *(float2*)&C[(size_t)row * N + col] =
                        make_float2(v0 * WSI + bv.x + rv.x, v1 * WSI + bv.y + rv.y);
                } else if (OP == 2) {
                    float2 bv = *(const float2*)&bias[col];
                    float w0 = fmaxf(v0 * WSI + bv.x, 0.0f);
                    float w1 = fmaxf(v1 * WSI + bv.y, 0.0f);
                    *(__half2*)&C0[(size_t)row * N + col] = __floats2half2_rn(w0, w1);
                } else {
                    *(__half2*)&Cout[(size_t)row * N + col] =
                        __floats2half2_rn(v0 * oscale, v1 * oscale);
                }
            }
        }
    }
}

// ======================= Tensor-core causal flash attention ====================
// q, K, V single fp16; 3-stage KV ring, 1 sync per k-tile; LPT scheduling.
#define AROWB 144
#define AQTILE (128*AROWB)    // 18432
#define AKTILE (64*AROWB)     // 9216
#define ASM_Q  0
#define ASM_KV AQTILE
#define AKV_K  0
#define AKV_V  AKTILE
#define AKVSTAGE (2*AKTILE)   // 18432
#define ANSTAGE 3
#define ASMEM (AQTILE + ANSTAGE*AKVSTAGE)  // 73728

__global__ __launch_bounds__(256, 2) void attn_tc(
    const fp16* __restrict__ Q,
    const fp16* __restrict__ Kg,
    const fp16* __restrict__ V,
    fp16* __restrict__ Y)
{
    extern __shared__ __align__(128) unsigned char asmem[];
    uint32_t sb = s2u(asmem);
    int tid = threadIdx.x, lane = tid & 31, wid = tid >> 5;
    int qt = gridDim.x - 1 - blockIdx.x;   // LPT: big tiles first
    int bh = blockIdx.y;
    int b = bh >> 4, h = bh & 15;

    size_t rowbase = (size_t)b * T_;
    size_t qoff = (rowbase + qt * 128) * E_ + h * HS_;

    {
        int chb = tid * 4;
        #pragma unroll
        for (int i = 0; i < 4; i++) {
            int lr = (chb + i) >> 3;
            int lc = (chb + i) & 7;
            uint32_t so = (uint32_t)(lr * AROWB + lc * 16);
            cp16(sb + ASM_Q + so, Q + qoff + (size_t)lr * E_ + lc * 8);
        }
    }
    asm volatile("cp.async.commit_group;" ::: "memory");

    int kv_row = tid >> 2;
    int kv_c   = (tid & 3) * 2;
    uint32_t kv_so = (uint32_t)(kv_row * AROWB + kv_c * 16);

    auto load_kv = [&](int kt, int buf) {
        size_t ko = (rowbase + kt * 64 + kv_row) * E_ + h * HS_ + kv_c * 8;
        uint32_t base = sb + ASM_KV + buf * AKVSTAGE + kv_so;
        cp16(base + AKV_K,      Kg + ko);
        cp16(base + AKV_K + 16, Kg + ko + 8);
        cp16(base + AKV_V,      V + ko);
        cp16(base + AKV_V + 16, V + ko + 8);
        asm volatile("cp.async.commit_group;" ::: "memory");
    };
    int nkt = 2 * qt + 2;   // >= 2 always
    load_kv(0, 0);
    load_kv(1, 1);

    // wait for Q (kv0, kv1 may stay in flight)
    asm volatile("cp.async.wait_group 2;" ::: "memory");
    __syncthreads();

    uint32_t a_row = (uint32_t)(wid * 16 + (lane & 15));
    uint32_t a_cb  = (uint32_t)((lane >> 4) * 16);
    uint32_t qf[4][4];
    #pragma unroll
    for (int s = 0; s < 4; s++)
        ldm4(qf[s], sb + ASM_Q + a_row * AROWB + s * 32 + a_cb);

    float oacc[8][4];
    #pragma unroll
    for (int i = 0; i < 8; i++)
        #pragma unroll
        for (int j = 0; j < 4; j++) oacc[i][j] = 0.f;
    float m0 = -1e30f, m1 = -1e30f, l0 = 0.f, l1 = 0.f;

    uint32_t b_rowo = (uint32_t)((lane & 7) + ((lane >> 4) & 1) * 8);
    uint32_t b_cbo  = (uint32_t)(((lane >> 3) & 1) * 16);
    uint32_t v_rowo = (uint32_t)(lane & 15);
    uint32_t v_cbo  = (uint32_t)(((lane >> 4) & 1) * 16);

    for (int kt = 0; kt < nkt; kt++) {
        if (kt + 1 < nkt) { asm volatile("cp.async.wait_group 1;" ::: "memory"); }
        else              { asm volatile("cp.async.wait_group 0;" ::: "memory"); }
        __syncthreads();
        if (kt + 2 < nkt) load_kv(kt + 2, (kt + 2) % ANSTAGE);

        uint32_t kb = sb + ASM_KV + (kt % ANSTAGE) * AKVSTAGE;

        float sacc[8][4];
        #pragma unroll
        for (int j = 0; j < 8; j++)
            #pragma unroll
            for (int q = 0; q < 4; q++) sacc[j][q] = 0.f;

        #pragma unroll
        for (int s = 0; s < 4; s++) {
            #pragma unroll
            for (int np = 0; np < 4; np++) {
                uint32_t bo = (uint32_t)(np * 16 + b_rowo) * AROWB + s * 32 + b_cbo;
                uint32_t kf[4];
                ldm4(kf, kb + AKV_K + bo);
                #pragma unroll
                for (int hf = 0; hf < 2; hf++)
                    mma_f16(sacc[np*2+hf], qf[s], kf[hf*2], kf[hf*2+1]);
            }
        }

        if (kt >= 2 * qt) {
            int qr0 = qt * 128 + wid * 16 + (lane >> 2);
            int kc  = kt * 64 + (lane & 3) * 2;
            #pragma unroll
            for (int j = 0; j < 8; j++) {
                int k0i = kc + j * 8;
                if (k0i     > qr0)     sacc[j][0] = -1e30f;
                if (k0i + 1 > qr0)     sacc[j][1] = -1e30f;
                if (k0i     > qr0 + 8) sacc[j][2] = -1e30f;
                if (k0i + 1 > qr0 + 8) sacc[j][3] = -1e30f;
            }
        }

        float mx0 = m0, mx1 = m1;
        #pragma unroll
        for (int j = 0; j < 8; j++) {
            mx0 = fmaxf(mx0, fmaxf(sacc[j][0], sacc[j][1]));
            mx1 = fmaxf(mx1, fmaxf(sacc[j][2], sacc[j][3]));
        }
        mx0 = fmaxf(mx0, __shfl_xor_sync(0xFFFFFFFFu, mx0, 1));
        mx0 = fmaxf(mx0, __shfl_xor_sync(0xFFFFFFFFu, mx0, 2));
        mx1 = fmaxf(mx1, __shfl_xor_sync(0xFFFFFFFFu, mx1, 1));
        mx1 = fmaxf(mx1, __shfl_xor_sync(0xFFFFFFFFu, mx1, 2));
        float cor0 = __expf(m0 - mx0);
        float cor1 = __expf(m1 - mx1);
        m0 = mx0; m1 = mx1;
        float rs0 = 0.f, rs1 = 0.f;
        #pragma unroll
        for (int j = 0; j < 8; j++) {
            float p0 = __expf(sacc[j][0] - m0);
            float p1 = __expf(sacc[j][1] - m0);
            float p2 = __expf(sacc[j][2] - m1);
            float p3 = __expf(sacc[j][3] - m1);
            sacc[j][0] = p0; sacc[j][1] = p1; sacc[j][2] = p2; sacc[j][3] = p3;
            rs0 += p0 + p1; rs1 += p2 + p3;
        }
        rs0 += __shfl_xor_sync(0xFFFFFFFFu, rs0, 1);
        rs0 += __shfl_xor_sync(0xFFFFFFFFu, rs0, 2);
        rs1 += __shfl_xor_sync(0xFFFFFFFFu, rs1, 1);
        rs1 += __shfl_xor_sync(0xFFFFFFFFu, rs1, 2);
        l0 = l0 * cor0 + rs0;
        l1 = l1 * cor1 + rs1;
        #pragma unroll
        for (int dt = 0; dt < 8; dt++) {
            oacc[dt][0] *= cor0; oacc[dt][1] *= cor0;
            oacc[dt][2] *= cor1; oacc[dt][3] *= cor1;
        }

        #pragma unroll
        for (int s = 0; s < 4; s++) {
            uint32_t pah[4];
            #pragma unroll
            for (int tt = 0; tt < 2; tt++) {
                const float* sc = sacc[2*s + tt];
                pah[tt*2+0] = packh(sc[0], sc[1]);
                pah[tt*2+1] = packh(sc[2], sc[3]);
            }
            #pragma unroll
            for (int dc = 0; dc < 4; dc++) {
                uint32_t vo = (uint32_t)(s * 16 + v_rowo) * AROWB + dc * 32 + v_cbo;
                uint32_t vf[4];
                ldm4t(vf, kb + AKV_V + vo);
                mma_f16(oacc[dc*2+0], pah, vf[0], vf[1]);
                mma_f16(oacc[dc*2+1], pah, vf[2], vf[3]);
            }
        }
    }

    float inv0 = 1.0f / l0;
    float inv1 = 1.0f / l1;
    int qr = qt * 128 + wid * 16 + (lane >> 2);
    size_t y0 = (rowbase + qr) * E_ + h * HS_ + (lane & 3) * 2;
    size_t y1 = y0 + (size_t)8 * E_;
    #pragma unroll
    for (int dt = 0; dt < 8; dt++) {
        *(__half2*)(Y + y0 + dt*8) = __floats2half2_rn(oacc[dt][0]*inv0, oacc[dt][1]*inv0);
        *(__half2*)(Y + y1 + dt*8) = __floats2half2_rn(oacc[dt][2]*inv1, oacc[dt][3]*inv1);
    }
}

// ======================= launch =======================
extern "C" void kernel_launch(void* const* d_in, const int* in_sizes, int n_in,
                              void* d_out, int out_size)
{
    const float* x    = (const float*)d_in[0];
    const float* Wq   = (const float*)d_in[1];
    const float* Wk   = (const float*)d_in[2];
    const float* Wv   = (const float*)d_in[3];
    const float* Wo   = (const float*)d_in[4];
    const float* bo   = (const float*)d_in[5];
    const float* ln1w = (const float*)d_in[6];
    const float* ln2w = (const float*)d_in[7];
    const float* W1   = (const float*)d_in[8];
    const float* b1   = (const float*)d_in[9];
    const float* W2   = (const float*)d_in[10];
    const float* b2   = (const float*)d_in[11];
    float* out = (float*)d_out;

    unsigned char* pool;
    cudaGetSymbolAddress((void**)&pool, g_pool);

    fp16*  hh   = (fp16*)(pool + O_H);
    fp16*  q    = (fp16*)(pool + O_Q);
    fp16*  k    = (fp16*)(pool + O_K);
    fp16*  v    = (fp16*)(pool + O_V);
    fp16*  y    = (fp16*)(pool + O_Y);
    float* x2   = (float*)(pool + O_X2);
    fp16*  ff   = (fp16*)(pool + O_FF);
    fp16*  wq   = (fp16*)(pool + O_WQ);
    fp16*  wk   = (fp16*)(pool + O_WK);
    fp16*  wv   = (fp16*)(pool + O_WV);
    fp16*  wo   = (fp16*)(pool + O_WO);
    fp16*  w1   = (fp16*)(pool + O_W1);
    fp16*  w2   = (fp16*)(pool + O_W2);

    cudaFuncSetAttribute((const void*)gemm_tc<1>, cudaFuncAttributeMaxDynamicSharedMemorySize, SMEM_SZ);
    cudaFuncSetAttribute((const void*)gemm_tc<2>, cudaFuncAttributeMaxDynamicSharedMemorySize, SMEM_SZ);
    cudaFuncSetAttribute((const void*)gemm_tc<3>, cudaFuncAttributeMaxDynamicSharedMemorySize, SMEM_SZ);
    cudaFuncSetAttribute((const void*)attn_tc,    cudaFuncAttributeMaxDynamicSharedMemorySize, ASMEM);

    dim3 gE (E_  / BN, M_ / BM);       // (8, 64)
    dim3 gQKV(3 * (E_ / BN), M_ / BM); // (24, 64)
    dim3 g4E(FF_ / BN, M_ / BM);       // (32, 64)

    // all weight converts in ONE launch
    wconv_all<<<12288, 256>>>(Wq, Wk, Wv, Wo, W1, W2, wq, wk, wv, wo, w1, w2);
    // h = LN1(x)
    ln_kernel<<<M_, 256>>>(x, ln1w, hh);
    // fused q,k,v projections -> single fp16 each (q pre-scaled by E^-0.5)
    gemm_tc<3><<<gQKV, 256, SMEM_SZ>>>(hh,
        wq, wk, wv,
        nullptr, nullptr, nullptr,
        q, k, v, M_, E_, E_);
    // y = causal attention
    attn_tc<<<dim3(T_/128, B_*H_), 256, ASMEM>>>(q, k, v, y);
    // x2 = x + y @ Wo + bo
    gemm_tc<1><<<gE, 256, SMEM_SZ>>>(y,
        wo, wo, wo,
        bo, x, x2,
        nullptr, nullptr, nullptr, M_, E_, E_);
    // h2 = LN2(x2)
    ln_kernel<<<M_, 256>>>(x2, ln2w, hh);
    // ff = relu(h2 @ W1 + b1)
    gemm_tc<2><<<g4E, 256, SMEM_SZ>>>(hh,
        w1, w1, w1,
        b1, nullptr, nullptr,
        ff, nullptr, nullptr, M_, FF_, E_);
    // out = x2 + ff @ W2 + b2
    gemm_tc<1><<<gE, 256, SMEM_SZ>>>(ff,
        w2, w2, w2,
        b2, x2, out,
        nullptr, nullptr, nullptr, M_, E_, FF_);
}